// round 1
// baseline (speedup 1.0000x reference)
#include <cuda_runtime.h>
#include <math.h>

#define NB 64
#define NS 257
#define ND 768
#define NH 12
#define HD 64
#define NTOK (NB*NS)          /* 16448 */
#define NQKV (NTOK*ND)        /* 12632064 */
#define NBH (NB*NH)           /* 768 */
#define EPSV 1e-10f
#define LAMDA 0.475f

// ---------------- device scratch (no allocations allowed) ----------------
__device__ float g_qkv[3*NQKV];     // q | k | v, each in (B,H,S,HD) layout
__device__ float g_ctx[NQKV];       // (B,S,D) layout
__device__ float g_ent[NBH*NS];     // entropy row, [0]=1
__device__ float g_loss1[NBH];
__device__ float g_loss2[NBH];

// =====================================================================
// Tiled SGEMM: C[M,N] = A[M,K] @ W[K,N] + bias[N]
// BM=128, BN=128, BK=8, 256 threads, 8x8 micro-tile.
// MODE 0: C row-major (m*N+n). MODE 1: qkv layout (B,H,S,HD).
// =====================================================================
template<int MODE>
__global__ void gemm128(const float* __restrict__ A, const float* __restrict__ W,
                        const float* __restrict__ bias, float* __restrict__ C,
                        int M, int N, int K)
{
    __shared__ __align__(16) float As[8][128];
    __shared__ __align__(16) float Bs[8][128];

    const int tid   = threadIdx.x;
    const int mBase = blockIdx.y * 128;
    const int nBase = blockIdx.x * 128;

    const int aRow = tid >> 1;            // 0..127
    const int aCol = (tid & 1) * 4;       // 0 or 4
    const int bRow = tid >> 5;            // 0..7
    const int bCol = (tid & 31) * 4;      // 0..124
    const int tr   = tid >> 4;            // 0..15
    const int tc   = tid & 15;            // 0..15

    const bool aValid = (mBase + aRow) < M;

    float acc[8][8];
    #pragma unroll
    for (int i = 0; i < 8; ++i)
        #pragma unroll
        for (int j = 0; j < 8; ++j) acc[i][j] = 0.f;

    for (int k0 = 0; k0 < K; k0 += 8) {
        float4 av = make_float4(0.f, 0.f, 0.f, 0.f);
        if (aValid)
            av = *(const float4*)(A + (size_t)(mBase + aRow) * K + k0 + aCol);
        As[aCol+0][aRow] = av.x;
        As[aCol+1][aRow] = av.y;
        As[aCol+2][aRow] = av.z;
        As[aCol+3][aRow] = av.w;

        *(float4*)&Bs[bRow][bCol] =
            *(const float4*)(W + (size_t)(k0 + bRow) * N + nBase + bCol);

        __syncthreads();

        #pragma unroll
        for (int kk = 0; kk < 8; ++kk) {
            float ra[8], rb[8];
            float4 a0 = *(const float4*)&As[kk][tr*8];
            float4 a1 = *(const float4*)&As[kk][tr*8+4];
            ra[0]=a0.x; ra[1]=a0.y; ra[2]=a0.z; ra[3]=a0.w;
            ra[4]=a1.x; ra[5]=a1.y; ra[6]=a1.z; ra[7]=a1.w;
            float4 b0 = *(const float4*)&Bs[kk][tc*8];
            float4 b1 = *(const float4*)&Bs[kk][tc*8+4];
            rb[0]=b0.x; rb[1]=b0.y; rb[2]=b0.z; rb[3]=b0.w;
            rb[4]=b1.x; rb[5]=b1.y; rb[6]=b1.z; rb[7]=b1.w;
            #pragma unroll
            for (int i = 0; i < 8; ++i)
                #pragma unroll
                for (int j = 0; j < 8; ++j)
                    acc[i][j] = fmaf(ra[i], rb[j], acc[i][j]);
        }
        __syncthreads();
    }

    #pragma unroll
    for (int i = 0; i < 8; ++i) {
        int m = mBase + tr*8 + i;
        if (m >= M) continue;
        #pragma unroll
        for (int j = 0; j < 8; ++j) {
            int n = nBase + tc*8 + j;
            float val = acc[i][j] + bias[n];
            if (MODE == 0) {
                C[(size_t)m * N + n] = val;
            } else {
                int b = m / NS, s = m % NS;
                int hh = n >> 6, hd = n & 63;
                C[(((size_t)b * NH + hh) * NS + s) * HD + hd] = val;
            }
        }
    }
}

// =====================================================================
// Adversarial probe kernel: one block per (b,h).
// Computes p1 (per-token MLP), p2 (per-patch MLP on merged 4-token feats),
// entropy row, and per-block loss partial sums.
// =====================================================================
__global__ void adv_kernel(const float* __restrict__ A1, const float* __restrict__ a1,
                           const float* __restrict__ A2, const float* __restrict__ a2,
                           const float* __restrict__ B1, const float* __restrict__ b1,
                           const float* __restrict__ B2, const float* __restrict__ b2)
{
    extern __shared__ float sm[];
    float* sm_ft  = sm;                  // 64*257 (featT[d][t], stride 257)
    float* sm_p1  = sm + 64*257;         // 256
    float* sm_p2  = sm_p1 + 256;         // 64
    float* sm_red = sm_p2 + 64;          // 16

    const int bh   = blockIdx.x;
    const int tid  = threadIdx.x;
    const int lane = tid & 31;
    const int w    = tid >> 5;

    // k tokens 1..256 of this (b,h)
    const float* kbase = g_qkv + (size_t)NQKV + (size_t)bh * NS * HD + HD;
    for (int i = tid; i < 256*64; i += 256) {
        int t = i >> 6, d = i & 63;
        sm_ft[d*NS + t] = kbase[i];
    }
    __syncthreads();

    float lsum1 = 0.f;
    // ---- p1: 8 passes, each warp handles 4 tokens, lanes split j over 512
    for (int pass = 0; pass < 8; ++pass) {
        int tbase = (pass*8 + w) * 4;
        float h[4][16];
        #pragma unroll
        for (int jj = 0; jj < 16; ++jj) {
            float av = a1[jj*32 + lane];
            #pragma unroll
            for (int tt = 0; tt < 4; ++tt) h[tt][jj] = av;
        }
        for (int d = 0; d < 64; ++d) {
            float f0 = sm_ft[d*NS + tbase + 0];
            float f1 = sm_ft[d*NS + tbase + 1];
            float f2 = sm_ft[d*NS + tbase + 2];
            float f3 = sm_ft[d*NS + tbase + 3];
            #pragma unroll
            for (int jj = 0; jj < 16; ++jj) {
                float wgt = A1[d*512 + jj*32 + lane];
                h[0][jj] = fmaf(f0, wgt, h[0][jj]);
                h[1][jj] = fmaf(f1, wgt, h[1][jj]);
                h[2][jj] = fmaf(f2, wgt, h[2][jj]);
                h[3][jj] = fmaf(f3, wgt, h[3][jj]);
            }
        }
        #pragma unroll
        for (int tt = 0; tt < 4; ++tt) {
            float s = 0.f;
            #pragma unroll
            for (int jj = 0; jj < 16; ++jj)
                s = fmaf(fmaxf(h[tt][jj], 0.f), A2[jj*32 + lane], s);
            #pragma unroll
            for (int o = 16; o > 0; o >>= 1) s += __shfl_xor_sync(0xffffffffu, s, o);
            float p = 1.f / (1.f + expf(-(s + a2[0])));
            if (lane == 0) {
                sm_p1[tbase + tt] = p;
                lsum1 += logf(fmaxf(1.f - p, EPSV));
            }
        }
    }

    float lsum2 = 0.f;
    // ---- p2: 2 passes, each warp handles 4 patches (merged 256-dim feats)
    for (int pass = 0; pass < 2; ++pass) {
        int mbase = (pass*8 + w) * 4;
        float h[4][16];
        #pragma unroll
        for (int jj = 0; jj < 16; ++jj) {
            float bv = b1[jj*32 + lane];
            #pragma unroll
            for (int tt = 0; tt < 4; ++tt) h[tt][jj] = bv;
        }
        #pragma unroll
        for (int q = 0; q < 4; ++q) {
            int toks[4];
            #pragma unroll
            for (int tt = 0; tt < 4; ++tt) {
                int m  = mbase + tt;
                int r2 = m >> 3, c2 = m & 7;
                toks[tt] = (2*r2 + (q >> 1)) * 16 + 2*c2 + (q & 1);
            }
            for (int d = 0; d < 64; ++d) {
                float f0 = sm_ft[d*NS + toks[0]];
                float f1 = sm_ft[d*NS + toks[1]];
                float f2 = sm_ft[d*NS + toks[2]];
                float f3 = sm_ft[d*NS + toks[3]];
                int kk = q*64 + d;
                #pragma unroll
                for (int jj = 0; jj < 16; ++jj) {
                    float wgt = B1[kk*512 + jj*32 + lane];
                    h[0][jj] = fmaf(f0, wgt, h[0][jj]);
                    h[1][jj] = fmaf(f1, wgt, h[1][jj]);
                    h[2][jj] = fmaf(f2, wgt, h[2][jj]);
                    h[3][jj] = fmaf(f3, wgt, h[3][jj]);
                }
            }
        }
        #pragma unroll
        for (int tt = 0; tt < 4; ++tt) {
            float s = 0.f;
            #pragma unroll
            for (int jj = 0; jj < 16; ++jj)
                s = fmaf(fmaxf(h[tt][jj], 0.f), B2[jj*32 + lane], s);
            #pragma unroll
            for (int o = 16; o > 0; o >>= 1) s += __shfl_xor_sync(0xffffffffu, s, o);
            float p = 1.f / (1.f + expf(-(s + b2[0])));
            if (lane == 0) {
                sm_p2[mbase + tt] = p;
                lsum2 += logf(fmaxf(1.f - p, EPSV));
            }
        }
    }

    if (lane == 0) { sm_red[w] = lsum1; sm_red[8 + w] = lsum2; }
    __syncthreads();

    // ---- entropy: 256 threads, one token each
    {
        int t = tid;
        float p1v = sm_p1[t];
        int gr = t >> 4, gc = t & 15;
        int m  = (gr >> 1) * 8 + (gc >> 1);
        float ad  = (1.f - LAMDA) * p1v + LAMDA * sm_p2[m];
        float ent = -ad * log2f(ad + EPSV) - (1.f - ad) * log2f(1.f - ad + EPSV);
        g_ent[bh*NS + 1 + t] = ent;
    }
    if (tid == 0) {
        g_ent[bh*NS] = 1.f;
        float s1 = 0.f, s2 = 0.f;
        #pragma unroll
        for (int i = 0; i < 8; ++i) { s1 += sm_red[i]; s2 += sm_red[8 + i]; }
        g_loss1[bh] = s1;
        g_loss2[bh] = s2;
    }
}

// =====================================================================
// Attention: one block per (b,h). K^T and V cached in SMEM.
// Warp per query: scores -> softmax -> (entropy scale on q==0) -> ctx.
// =====================================================================
__global__ void attn_kernel()
{
    extern __shared__ float sm[];
    float* sm_kT = sm;                    // [64][257]
    float* sm_v  = sm + 64*NS;            // [257][64]
    float* sm_p  = sm_v + NS*64;          // [8][257]

    const int bh   = blockIdx.x;
    const int tid  = threadIdx.x;
    const int lane = tid & 31;
    const int w    = tid >> 5;

    const float* qb = g_qkv + (size_t)bh * NS * HD;
    const float* kb = g_qkv + (size_t)NQKV + (size_t)bh * NS * HD;
    const float* vb = g_qkv + (size_t)2*NQKV + (size_t)bh * NS * HD;

    for (int i = tid; i < NS*64; i += 256) {
        int t = i >> 6, d = i & 63;
        sm_kT[d*NS + t] = kb[i];
        sm_v[i]         = vb[i];
    }
    __syncthreads();

    const int b = bh / NH, h = bh % NH;

    for (int s = w; s < NS; s += 8) {
        float q[64];
        #pragma unroll
        for (int d = 0; d < 64; ++d) q[d] = qb[s*64 + d];

        float sc[9];
        #pragma unroll
        for (int c = 0; c < 9; ++c) {
            int kt = lane + 32*c;
            float acc = -1e30f;
            if (kt < NS) {
                acc = 0.f;
                #pragma unroll
                for (int d = 0; d < 64; ++d)
                    acc = fmaf(q[d], sm_kT[d*NS + kt], acc);
                acc *= 0.125f;
            }
            sc[c] = acc;
        }
        float mx = sc[0];
        #pragma unroll
        for (int c = 1; c < 9; ++c) mx = fmaxf(mx, sc[c]);
        #pragma unroll
        for (int o = 16; o > 0; o >>= 1) mx = fmaxf(mx, __shfl_xor_sync(0xffffffffu, mx, o));

        float sum = 0.f;
        #pragma unroll
        for (int c = 0; c < 9; ++c) {
            int kt = lane + 32*c;
            float e = (kt < NS) ? expf(sc[c] - mx) : 0.f;
            sc[c] = e;
            sum += e;
        }
        #pragma unroll
        for (int o = 16; o > 0; o >>= 1) sum += __shfl_xor_sync(0xffffffffu, sum, o);
        float inv = 1.f / sum;

        __syncwarp();
        #pragma unroll
        for (int c = 0; c < 9; ++c) {
            int kt = lane + 32*c;
            if (kt < NS) {
                float p = sc[c] * inv;
                if (s == 0) p *= g_ent[bh*NS + kt];
                sm_p[w*NS + kt] = p;
            }
        }
        __syncwarp();

        float acc0 = 0.f, acc1 = 0.f;
        for (int kt = 0; kt < NS; ++kt) {
            float pv = sm_p[w*NS + kt];
            acc0 = fmaf(pv, sm_v[kt*64 + lane],      acc0);
            acc1 = fmaf(pv, sm_v[kt*64 + 32 + lane], acc1);
        }
        float* cp = g_ctx + ((size_t)(b*NS + s)) * ND + h*HD;
        cp[lane]      = acc0;
        cp[32 + lane] = acc1;
        __syncwarp();
    }
}

// =====================================================================
// Final deterministic loss reduction
// =====================================================================
__global__ void loss_kernel(float* __restrict__ out)
{
    __shared__ float s1[256], s2[256];
    int tid = threadIdx.x;
    float a = 0.f, b = 0.f;
    for (int i = tid; i < NBH; i += 256) { a += g_loss1[i]; b += g_loss2[i]; }
    s1[tid] = a; s2[tid] = b;
    __syncthreads();
    for (int o = 128; o > 0; o >>= 1) {
        if (tid < o) { s1[tid] += s1[tid + o]; s2[tid] += s2[tid + o]; }
        __syncthreads();
    }
    if (tid == 0)
        out[0] = -s1[0] / ((float)NBH * 256.f) - s2[0] / ((float)NBH * 64.f);
}

// =====================================================================
// Launch
// =====================================================================
extern "C" void kernel_launch(void* const* d_in, const int* in_sizes, int n_in,
                              void* d_out, int out_size)
{
    const float* X  = (const float*)d_in[0];
    const float* Wq = (const float*)d_in[1];
    const float* bq = (const float*)d_in[2];
    const float* Wk = (const float*)d_in[3];
    const float* bk = (const float*)d_in[4];
    const float* Wv = (const float*)d_in[5];
    const float* bv = (const float*)d_in[6];
    const float* Wo = (const float*)d_in[7];
    const float* bo = (const float*)d_in[8];
    const float* A1 = (const float*)d_in[9];
    const float* a1 = (const float*)d_in[10];
    const float* A2 = (const float*)d_in[11];
    const float* a2 = (const float*)d_in[12];
    const float* B1 = (const float*)d_in[13];
    const float* b1 = (const float*)d_in[14];
    const float* B2 = (const float*)d_in[15];
    const float* b2 = (const float*)d_in[16];
    float* out = (float*)d_out;

    float *qkv = nullptr, *ctx = nullptr;
    cudaGetSymbolAddress((void**)&qkv, g_qkv);
    cudaGetSymbolAddress((void**)&ctx, g_ctx);

    const int ATTN_SMEM = (64*NS + NS*64 + 8*NS) * 4;   // 139808 B
    const int ADV_SMEM  = (64*NS + 256 + 64 + 16) * 4;  // 67136 B
    cudaFuncSetAttribute(attn_kernel, cudaFuncAttributeMaxDynamicSharedMemorySize, ATTN_SMEM);
    cudaFuncSetAttribute(adv_kernel,  cudaFuncAttributeMaxDynamicSharedMemorySize, ADV_SMEM);

    dim3 ggrid(ND/128, (NTOK + 127)/128);   // (6, 129)

    gemm128<1><<<ggrid, 256>>>(X, Wq, bq, qkv,            NTOK, ND, ND);
    gemm128<1><<<ggrid, 256>>>(X, Wk, bk, qkv + NQKV,     NTOK, ND, ND);
    gemm128<1><<<ggrid, 256>>>(X, Wv, bv, qkv + 2*NQKV,   NTOK, ND, ND);

    adv_kernel<<<NBH, 256, ADV_SMEM>>>(A1, a1, A2, a2, B1, b1, B2, b2);
    attn_kernel<<<NBH, 256, ATTN_SMEM>>>();

    gemm128<0><<<ggrid, 256>>>(ctx, Wo, bo, out, NTOK, ND, ND);

    if (out_size > NQKV)
        loss_kernel<<<1, 256>>>(out + (out_size - 1));
}

// round 2
// speedup vs baseline: 1.9361x; 1.9361x over previous
#include <cuda_runtime.h>
#include <math.h>

#define NB 64
#define NS 257
#define ND 768
#define NH 12
#define HD 64
#define NTOK (NB*NS)          /* 16448 */
#define NQKV (NTOK*ND)        /* 12632064 */
#define NBH (NB*NH)           /* 768 */
#define EPSV 1e-10f
#define LAMDA 0.475f

// ---------------- device scratch (no allocations allowed) ----------------
__device__ float g_qkv[3*NQKV];            // q | k | v, each (B,H,S,HD)
__device__ float g_ctx[NQKV];              // (B,S,D)
__device__ float g_ent[NBH*NS];            // entropy row, [0]=1
__device__ float g_p1[NBH*256];
__device__ float g_loss1[NBH];
__device__ float g_loss2[NBH];
__device__ float g_h1[(size_t)NBH*256*512];   // p1 hidden (402 MB)
__device__ float g_h2[(size_t)NBH*64*512];    // p2 hidden (100 MB)

// ---------------- tf32 helpers ----------------
__device__ __forceinline__ unsigned f2tf32(float x){
    unsigned r; asm("cvt.rna.tf32.f32 %0, %1;" : "=r"(r) : "f"(x)); return r;
}
__device__ __forceinline__ void mma_tf32(float* c,
    unsigned a0, unsigned a1, unsigned a2, unsigned a3,
    unsigned b0, unsigned b1)
{
    asm volatile(
      "mma.sync.aligned.m16n8k8.row.col.f32.tf32.tf32.f32 "
      "{%0,%1,%2,%3},{%4,%5,%6,%7},{%8,%9},{%0,%1,%2,%3};"
      : "+f"(c[0]), "+f"(c[1]), "+f"(c[2]), "+f"(c[3])
      : "r"(a0), "r"(a1), "r"(a2), "r"(a3), "r"(b0), "r"(b1));
}

// =====================================================================
// Tensor-core tf32 GEMM: C[M,N] = op(A)[M,K] @ W[K,N] (+bias, +relu, ...)
// BM=128, BN=128, BK=16, 256 threads (8 warps: 4 in M x 2 in N).
// AMODE 0: A row-major [M,K] (guard rows)
// AMODE 2: p1 feature gather from k: row m -> (bh=m>>8, t=m&255), lda=64
// AMODE 3: p2 merged-patch gather from k, K=256 (q,d decomposition)
// EMODE 0: C row-major + bias
// EMODE 1: qkv scatter (B,H,S,HD) + bias
// EMODE 2: relu(x + bias), row-major, no guard
// =====================================================================
template<int AMODE, int EMODE>
__global__ void __launch_bounds__(256)
gemm_tc(const float* __restrict__ A, const float* __restrict__ W,
        const float* __restrict__ bias, float* __restrict__ C,
        int M, int N, int K)
{
    __shared__ unsigned As[16][132];
    __shared__ unsigned Bs[16][132];

    const int tid  = threadIdx.x;
    const int lane = tid & 31;
    const int warp = tid >> 5;
    const int g    = lane >> 2;     // groupID 0..7
    const int t4   = lane & 3;      // thread-in-group 0..3
    const int wm   = (warp & 3) * 32;
    const int wn   = (warp >> 2) * 64;
    const int mBase = blockIdx.y * 128;
    const int nBase = blockIdx.x * 128;

    // global-load thread mapping
    const int aRow = tid >> 1;            // 0..127
    const int aK   = (tid & 1) * 8;       // 0 or 8
    const int bRow = tid >> 4;            // 0..15
    const int bCol = (tid & 15) * 8;      // 0..120

    // per-thread A row resolution
    long aOff = -1;      // base element offset of this A row (AMODE 0/2)
    int  rowbase = 0, pr2 = 0, pc2 = 0;   // AMODE 3 state
    if (AMODE == 0) {
        int m = mBase + aRow;
        if (m < M) aOff = (long)m * K;
    } else if (AMODE == 2) {
        int m  = mBase + aRow;
        int bh = m >> 8, t = m & 255;
        aOff = ((long)bh * NS + 1 + t) * HD;
    } else { // AMODE 3
        int m  = mBase + aRow;
        int bh = m >> 6, patch = m & 63;
        rowbase = bh * NS + 1;
        pr2 = patch >> 3; pc2 = patch & 7;
    }

    float ra[8], rb[8];

    auto loadAB = [&](int k0) {
        // ---- A: 8 floats
        if (AMODE == 3) {
            int kk = k0 + aK;
            int q = kk >> 6, d = kk & 63;
            int token = (2*pr2 + (q >> 1)) * 16 + 2*pc2 + (q & 1);
            const float4* p = (const float4*)(A + ((long)(rowbase + token)) * HD + d);
            float4 v0 = p[0], v1 = p[1];
            ra[0]=v0.x; ra[1]=v0.y; ra[2]=v0.z; ra[3]=v0.w;
            ra[4]=v1.x; ra[5]=v1.y; ra[6]=v1.z; ra[7]=v1.w;
        } else {
            if (aOff >= 0) {
                const float4* p = (const float4*)(A + aOff + k0 + aK);
                float4 v0 = p[0], v1 = p[1];
                ra[0]=v0.x; ra[1]=v0.y; ra[2]=v0.z; ra[3]=v0.w;
                ra[4]=v1.x; ra[5]=v1.y; ra[6]=v1.z; ra[7]=v1.w;
            } else {
                #pragma unroll
                for (int j = 0; j < 8; ++j) ra[j] = 0.f;
            }
        }
        // ---- B: 8 floats
        const float4* p = (const float4*)(W + (long)(k0 + bRow) * N + nBase + bCol);
        float4 v0 = p[0], v1 = p[1];
        rb[0]=v0.x; rb[1]=v0.y; rb[2]=v0.z; rb[3]=v0.w;
        rb[4]=v1.x; rb[5]=v1.y; rb[6]=v1.z; rb[7]=v1.w;
    };
    auto stageAB = [&]() {
        #pragma unroll
        for (int j = 0; j < 8; ++j) As[aK + j][aRow] = f2tf32(ra[j]);
        #pragma unroll
        for (int j = 0; j < 8; ++j) Bs[bRow][bCol + j] = f2tf32(rb[j]);
    };

    float acc[2][8][4];
    #pragma unroll
    for (int mt = 0; mt < 2; ++mt)
        #pragma unroll
        for (int nt = 0; nt < 8; ++nt)
            #pragma unroll
            for (int i = 0; i < 4; ++i) acc[mt][nt][i] = 0.f;

    loadAB(0);
    stageAB();
    __syncthreads();

    for (int k0 = 0; k0 < K; k0 += 16) {
        const bool more = (k0 + 16) < K;
        if (more) loadAB(k0 + 16);

        #pragma unroll
        for (int ks = 0; ks < 2; ++ks) {
            const int kr = ks * 8;
            unsigned af[2][4];
            #pragma unroll
            for (int mt = 0; mt < 2; ++mt) {
                int m0 = wm + mt * 16;
                af[mt][0] = As[kr + t4    ][m0 + g    ];
                af[mt][1] = As[kr + t4    ][m0 + g + 8];
                af[mt][2] = As[kr + t4 + 4][m0 + g    ];
                af[mt][3] = As[kr + t4 + 4][m0 + g + 8];
            }
            #pragma unroll
            for (int nt = 0; nt < 8; ++nt) {
                int n0 = wn + nt * 8 + g;
                unsigned b0 = Bs[kr + t4    ][n0];
                unsigned b1 = Bs[kr + t4 + 4][n0];
                mma_tf32(acc[0][nt], af[0][0], af[0][1], af[0][2], af[0][3], b0, b1);
                mma_tf32(acc[1][nt], af[1][0], af[1][1], af[1][2], af[1][3], b0, b1);
            }
        }
        if (more) {
            __syncthreads();
            stageAB();
            __syncthreads();
        }
    }

    // ---- epilogue
    #pragma unroll
    for (int mt = 0; mt < 2; ++mt) {
        int r0 = mBase + wm + mt * 16 + g;
        #pragma unroll
        for (int nt = 0; nt < 8; ++nt) {
            int c0 = nBase + wn + nt * 8 + 2 * t4;
            #pragma unroll
            for (int half = 0; half < 2; ++half) {
                int m = r0 + half * 8;
                float v0 = acc[mt][nt][half*2 + 0];
                float v1 = acc[mt][nt][half*2 + 1];
                if (EMODE == 2) {
                    float* cp = C + (long)m * N + c0;
                    cp[0] = fmaxf(v0 + bias[c0], 0.f);
                    cp[1] = fmaxf(v1 + bias[c0 + 1], 0.f);
                } else if (EMODE == 0) {
                    if (m < M) {
                        float* cp = C + (long)m * N + c0;
                        cp[0] = v0 + bias[c0];
                        cp[1] = v1 + bias[c0 + 1];
                    }
                } else { // EMODE 1: qkv scatter
                    if (m < M) {
                        int b = m / NS, s = m % NS;
                        int hh0 = c0 >> 6, hd0 = c0 & 63;
                        float* cp = g_qkv + ((((long)b * NH + hh0) * NS + s) * HD + hd0);
                        // c0 and c0+1 share the same head (c0 even, hd < 63)
                        long ofs = (long)(C - g_qkv); // C passed as offset base
                        cp += ofs;
                        cp[0] = v0 + bias[c0];
                        cp[1] = v1 + bias[c0 + 1];
                    }
                }
            }
        }
    }
}

// =====================================================================
// reduce_p1: p1 = sigmoid(h1 @ A2 + a2); store p1, per-bh loss1 partial
// =====================================================================
__global__ void reduce_p1(const float* __restrict__ A2, const float* __restrict__ a2)
{
    __shared__ float sred[8];
    const int bh = blockIdx.x;
    const int tid = threadIdx.x, lane = tid & 31, w = tid >> 5;

    float lsum = 0.f;
    for (int r = w * 32; r < w * 32 + 32; ++r) {
        const float* hp = g_h1 + ((size_t)bh * 256 + r) * 512;
        float s = 0.f;
        #pragma unroll
        for (int i = 0; i < 16; ++i)
            s = fmaf(hp[lane + 32*i], A2[lane + 32*i], s);
        #pragma unroll
        for (int o = 16; o > 0; o >>= 1) s += __shfl_xor_sync(0xffffffffu, s, o);
        if (lane == 0) {
            float p = 1.f / (1.f + expf(-(s + a2[0])));
            g_p1[bh * 256 + r] = p;
            lsum += logf(fmaxf(1.f - p, EPSV));
        }
    }
    if (lane == 0) sred[w] = lsum;
    __syncthreads();
    if (tid == 0) {
        float s = 0.f;
        #pragma unroll
        for (int i = 0; i < 8; ++i) s += sred[i];
        g_loss1[bh] = s;
    }
}

// =====================================================================
// reduce_p2 + entropy: p2 = sigmoid(h2 @ B2 + b2); loss2 partial; entropy row
// =====================================================================
__global__ void reduce_p2_ent(const float* __restrict__ B2, const float* __restrict__ b2)
{
    __shared__ float sm_p2[64];
    __shared__ float sred[8];
    const int bh = blockIdx.x;
    const int tid = threadIdx.x, lane = tid & 31, w = tid >> 5;

    float lsum = 0.f;
    for (int r = w * 8; r < w * 8 + 8; ++r) {
        const float* hp = g_h2 + ((size_t)bh * 64 + r) * 512;
        float s = 0.f;
        #pragma unroll
        for (int i = 0; i < 16; ++i)
            s = fmaf(hp[lane + 32*i], B2[lane + 32*i], s);
        #pragma unroll
        for (int o = 16; o > 0; o >>= 1) s += __shfl_xor_sync(0xffffffffu, s, o);
        if (lane == 0) {
            float p = 1.f / (1.f + expf(-(s + b2[0])));
            sm_p2[r] = p;
            lsum += logf(fmaxf(1.f - p, EPSV));
        }
    }
    if (lane == 0) sred[w] = lsum;
    __syncthreads();

    // entropy: one token per thread
    {
        int t = tid;
        float p1v = g_p1[bh * 256 + t];
        int gr = t >> 4, gc = t & 15;
        int m  = (gr >> 1) * 8 + (gc >> 1);
        float ad  = (1.f - LAMDA) * p1v + LAMDA * sm_p2[m];
        float ent = -ad * log2f(ad + EPSV) - (1.f - ad) * log2f(1.f - ad + EPSV);
        g_ent[bh * NS + 1 + t] = ent;
    }
    if (tid == 0) {
        g_ent[bh * NS] = 1.f;
        float s = 0.f;
        #pragma unroll
        for (int i = 0; i < 8; ++i) s += sred[i];
        g_loss2[bh] = s;
    }
}

// =====================================================================
// Attention: one block per (b,h). K^T and V cached in SMEM.
// =====================================================================
__global__ void attn_kernel()
{
    extern __shared__ float sm[];
    float* sm_kT = sm;                    // [64][257]
    float* sm_v  = sm + 64*NS;            // [257][64]
    float* sm_p  = sm_v + NS*64;          // [8][257]

    const int bh   = blockIdx.x;
    const int tid  = threadIdx.x;
    const int lane = tid & 31;
    const int w    = tid >> 5;

    const float* qb = g_qkv + (size_t)bh * NS * HD;
    const float* kb = g_qkv + (size_t)NQKV + (size_t)bh * NS * HD;
    const float* vb = g_qkv + (size_t)2*NQKV + (size_t)bh * NS * HD;

    for (int i = tid; i < NS*64; i += 256) {
        int t = i >> 6, d = i & 63;
        sm_kT[d*NS + t] = kb[i];
        sm_v[i]         = vb[i];
    }
    __syncthreads();

    const int b = bh / NH, h = bh % NH;

    for (int s = w; s < NS; s += 8) {
        float q[64];
        #pragma unroll
        for (int d = 0; d < 64; ++d) q[d] = qb[s*64 + d];

        float sc[9];
        #pragma unroll
        for (int c = 0; c < 9; ++c) {
            int kt = lane + 32*c;
            float acc = -1e30f;
            if (kt < NS) {
                acc = 0.f;
                #pragma unroll
                for (int d = 0; d < 64; ++d)
                    acc = fmaf(q[d], sm_kT[d*NS + kt], acc);
                acc *= 0.125f;
            }
            sc[c] = acc;
        }
        float mx = sc[0];
        #pragma unroll
        for (int c = 1; c < 9; ++c) mx = fmaxf(mx, sc[c]);
        #pragma unroll
        for (int o = 16; o > 0; o >>= 1) mx = fmaxf(mx, __shfl_xor_sync(0xffffffffu, mx, o));

        float sum = 0.f;
        #pragma unroll
        for (int c = 0; c < 9; ++c) {
            int kt = lane + 32*c;
            float e = (kt < NS) ? expf(sc[c] - mx) : 0.f;
            sc[c] = e;
            sum += e;
        }
        #pragma unroll
        for (int o = 16; o > 0; o >>= 1) sum += __shfl_xor_sync(0xffffffffu, sum, o);
        float inv = 1.f / sum;

        __syncwarp();
        #pragma unroll
        for (int c = 0; c < 9; ++c) {
            int kt = lane + 32*c;
            if (kt < NS) {
                float p = sc[c] * inv;
                if (s == 0) p *= g_ent[bh*NS + kt];
                sm_p[w*NS + kt] = p;
            }
        }
        __syncwarp();

        float acc0 = 0.f, acc1 = 0.f;
        for (int kt = 0; kt < NS; ++kt) {
            float pv = sm_p[w*NS + kt];
            acc0 = fmaf(pv, sm_v[kt*64 + lane],      acc0);
            acc1 = fmaf(pv, sm_v[kt*64 + 32 + lane], acc1);
        }
        float* cp = g_ctx + ((size_t)(b*NS + s)) * ND + h*HD;
        cp[lane]      = acc0;
        cp[32 + lane] = acc1;
        __syncwarp();
    }
}

// =====================================================================
// Final deterministic loss reduction
// =====================================================================
__global__ void loss_kernel(float* __restrict__ out)
{
    __shared__ float s1[256], s2[256];
    int tid = threadIdx.x;
    float a = 0.f, b = 0.f;
    for (int i = tid; i < NBH; i += 256) { a += g_loss1[i]; b += g_loss2[i]; }
    s1[tid] = a; s2[tid] = b;
    __syncthreads();
    for (int o = 128; o > 0; o >>= 1) {
        if (tid < o) { s1[tid] += s1[tid + o]; s2[tid] += s2[tid + o]; }
        __syncthreads();
    }
    if (tid == 0)
        out[0] = -s1[0] / ((float)NBH * 256.f) - s2[0] / ((float)NBH * 64.f);
}

// =====================================================================
// Launch
// =====================================================================
extern "C" void kernel_launch(void* const* d_in, const int* in_sizes, int n_in,
                              void* d_out, int out_size)
{
    const float* X  = (const float*)d_in[0];
    const float* Wq = (const float*)d_in[1];
    const float* bq = (const float*)d_in[2];
    const float* Wk = (const float*)d_in[3];
    const float* bk = (const float*)d_in[4];
    const float* Wv = (const float*)d_in[5];
    const float* bv = (const float*)d_in[6];
    const float* Wo = (const float*)d_in[7];
    const float* bo = (const float*)d_in[8];
    const float* A1 = (const float*)d_in[9];
    const float* a1 = (const float*)d_in[10];
    const float* A2 = (const float*)d_in[11];
    const float* a2 = (const float*)d_in[12];
    const float* B1 = (const float*)d_in[13];
    const float* b1 = (const float*)d_in[14];
    const float* B2 = (const float*)d_in[15];
    const float* b2 = (const float*)d_in[16];
    float* out = (float*)d_out;

    float *qkv = nullptr, *ctx = nullptr, *h1 = nullptr, *h2 = nullptr;
    cudaGetSymbolAddress((void**)&qkv, g_qkv);
    cudaGetSymbolAddress((void**)&ctx, g_ctx);
    cudaGetSymbolAddress((void**)&h1,  g_h1);
    cudaGetSymbolAddress((void**)&h2,  g_h2);
    float* kbase = qkv + NQKV;

    const int ATTN_SMEM = (64*NS + NS*64 + 8*NS) * 4;   // 139808 B
    cudaFuncSetAttribute(attn_kernel, cudaFuncAttributeMaxDynamicSharedMemorySize, ATTN_SMEM);

    dim3 gproj(ND/128, (NTOK + 127)/128);   // (6, 129)

    // QKV projections (EMODE 1 scatter). Pass qkv-region base so the scatter
    // lands in the right third (C is used as offset base inside EMODE 1).
    gemm_tc<0,1><<<gproj, 256>>>(X, Wq, bq, qkv,           NTOK, ND, ND);
    gemm_tc<0,1><<<gproj, 256>>>(X, Wk, bk, qkv + NQKV,    NTOK, ND, ND);
    gemm_tc<0,1><<<gproj, 256>>>(X, Wv, bv, qkv + 2*NQKV,  NTOK, ND, ND);

    // adversarial MLP layer 1 as batched GEMMs (tensor cores, fused relu)
    gemm_tc<2,2><<<dim3(512/128, (NBH*256)/128), 256>>>(kbase, A1, a1, h1, NBH*256, 512, 64);
    gemm_tc<3,2><<<dim3(512/128, (NBH*64)/128),  256>>>(kbase, B1, b1, h2, NBH*64,  512, 256);

    reduce_p1<<<NBH, 256>>>(A2, a2);
    reduce_p2_ent<<<NBH, 256>>>(B2, b2);

    attn_kernel<<<NBH, 256, ATTN_SMEM>>>();

    gemm_tc<0,0><<<gproj, 256>>>(ctx, Wo, bo, out, NTOK, ND, ND);

    if (out_size > NQKV)
        loss_kernel<<<1, 256>>>(out + (out_size - 1));
}

// round 3
// speedup vs baseline: 2.1382x; 1.1044x over previous
#include <cuda_runtime.h>
#include <math.h>

#define NB 64
#define NS 257
#define ND 768
#define NH 12
#define HD 64
#define NTOK (NB*NS)          /* 16448 */
#define NQKV (NTOK*ND)        /* 12632064 */
#define NBH (NB*NH)           /* 768 */
#define EPSV 1e-10f
#define LAMDA 0.475f

// ---------------- device scratch ----------------
__device__ float g_qkv[3*NQKV];            // q | k | v, each (B,H,S,HD)
__device__ float g_ctx[NQKV];              // (B,S,D)
__device__ float g_ent[NBH*NS];            // entropy row, [0]=1
__device__ float g_loss1[NBH];
__device__ float g_loss2[NBH];
__device__ float g_part1[(size_t)NBH*256*8];  // p1 layer-2 partial dots
__device__ float g_part2[(size_t)NBH*64*8];   // p2 layer-2 partial dots

// ---------------- tf32 helpers ----------------
__device__ __forceinline__ unsigned f2tf32(float x){
    unsigned r; asm("cvt.rna.tf32.f32 %0, %1;" : "=r"(r) : "f"(x)); return r;
}
__device__ __forceinline__ void mma_tf32(float* c,
    unsigned a0, unsigned a1, unsigned a2, unsigned a3,
    unsigned b0, unsigned b1)
{
    asm volatile(
      "mma.sync.aligned.m16n8k8.row.col.f32.tf32.tf32.f32 "
      "{%0,%1,%2,%3},{%4,%5,%6,%7},{%8,%9},{%0,%1,%2,%3};"
      : "+f"(c[0]), "+f"(c[1]), "+f"(c[2]), "+f"(c[3])
      : "r"(a0), "r"(a1), "r"(a2), "r"(a3), "r"(b0), "r"(b1));
}

// =====================================================================
// Tensor-core tf32 GEMM: BM=128, BN=128, BK=16, 256 threads, smem 2-stage.
// AMODE 0: A row-major [M,K] (guarded)
// AMODE 2: p1 feature gather (row m -> bh,t in k tensor), lda=64
// AMODE 3: p2 merged-patch gather (K=256 -> q,d decomposition)
// EMODE 0: C row-major + bias
// EMODE 1: qkv scatter (B,H,S,HD) + bias
// EMODE 3: fused relu + dot with W2 -> per-(row, col-slice) partials in C
// =====================================================================
template<int AMODE, int EMODE>
__global__ void __launch_bounds__(256)
gemm_tc(const float* __restrict__ A, const float* __restrict__ W,
        const float* __restrict__ bias, const float* __restrict__ W2,
        float* __restrict__ C, int M, int N, int K)
{
    __shared__ unsigned As[2][16][132];
    __shared__ unsigned Bs[2][16][132];

    const int tid  = threadIdx.x;
    const int lane = tid & 31;
    const int warp = tid >> 5;
    const int g    = lane >> 2;
    const int t4   = lane & 3;
    const int wm   = (warp & 3) * 32;
    const int wn   = (warp >> 2) * 64;
    const int mBase = blockIdx.y * 128;
    const int nBase = blockIdx.x * 128;

    const int aRow = tid >> 1;
    const int aK   = (tid & 1) * 8;
    const int bRow = tid >> 4;
    const int bCol = (tid & 15) * 8;

    long aOff = -1;
    int  rowbase = 0, pr2 = 0, pc2 = 0;
    if (AMODE == 0) {
        int m = mBase + aRow;
        if (m < M) aOff = (long)m * K;
    } else if (AMODE == 2) {
        int m  = mBase + aRow;
        int bh = m >> 8, t = m & 255;
        aOff = ((long)bh * NS + 1 + t) * HD;
    } else { // AMODE 3
        int m  = mBase + aRow;
        int bh = m >> 6, patch = m & 63;
        rowbase = bh * NS + 1;
        pr2 = patch >> 3; pc2 = patch & 7;
    }

    float ra[8], rb[8];

    auto loadAB = [&](int k0) {
        if (AMODE == 3) {
            int kk = k0 + aK;
            int q = kk >> 6, d = kk & 63;
            int token = (2*pr2 + (q >> 1)) * 16 + 2*pc2 + (q & 1);
            const float4* p = (const float4*)(A + ((long)(rowbase + token)) * HD + d);
            float4 v0 = p[0], v1 = p[1];
            ra[0]=v0.x; ra[1]=v0.y; ra[2]=v0.z; ra[3]=v0.w;
            ra[4]=v1.x; ra[5]=v1.y; ra[6]=v1.z; ra[7]=v1.w;
        } else {
            if (aOff >= 0) {
                const float4* p = (const float4*)(A + aOff + k0 + aK);
                float4 v0 = p[0], v1 = p[1];
                ra[0]=v0.x; ra[1]=v0.y; ra[2]=v0.z; ra[3]=v0.w;
                ra[4]=v1.x; ra[5]=v1.y; ra[6]=v1.z; ra[7]=v1.w;
            } else {
                #pragma unroll
                for (int j = 0; j < 8; ++j) ra[j] = 0.f;
            }
        }
        const float4* p = (const float4*)(W + (long)(k0 + bRow) * N + nBase + bCol);
        float4 v0 = p[0], v1 = p[1];
        rb[0]=v0.x; rb[1]=v0.y; rb[2]=v0.z; rb[3]=v0.w;
        rb[4]=v1.x; rb[5]=v1.y; rb[6]=v1.z; rb[7]=v1.w;
    };
    auto stageAB = [&](int buf) {
        #pragma unroll
        for (int j = 0; j < 8; ++j) As[buf][aK + j][aRow] = f2tf32(ra[j]);
        #pragma unroll
        for (int j = 0; j < 8; ++j) Bs[buf][bRow][bCol + j] = f2tf32(rb[j]);
    };

    float acc[2][8][4];
    #pragma unroll
    for (int mt = 0; mt < 2; ++mt)
        #pragma unroll
        for (int nt = 0; nt < 8; ++nt)
            #pragma unroll
            for (int i = 0; i < 4; ++i) acc[mt][nt][i] = 0.f;

    loadAB(0);
    stageAB(0);
    __syncthreads();
    int cur = 0;

    for (int k0 = 0; k0 < K; k0 += 16) {
        const bool more = (k0 + 16) < K;
        if (more) loadAB(k0 + 16);

        #pragma unroll
        for (int ks = 0; ks < 2; ++ks) {
            const int kr = ks * 8;
            unsigned af[2][4];
            #pragma unroll
            for (int mt = 0; mt < 2; ++mt) {
                int m0 = wm + mt * 16;
                af[mt][0] = As[cur][kr + t4    ][m0 + g    ];
                af[mt][1] = As[cur][kr + t4    ][m0 + g + 8];
                af[mt][2] = As[cur][kr + t4 + 4][m0 + g    ];
                af[mt][3] = As[cur][kr + t4 + 4][m0 + g + 8];
            }
            #pragma unroll
            for (int nt = 0; nt < 8; ++nt) {
                int n0 = wn + nt * 8 + g;
                unsigned b0 = Bs[cur][kr + t4    ][n0];
                unsigned b1 = Bs[cur][kr + t4 + 4][n0];
                mma_tf32(acc[0][nt], af[0][0], af[0][1], af[0][2], af[0][3], b0, b1);
                mma_tf32(acc[1][nt], af[1][0], af[1][1], af[1][2], af[1][3], b0, b1);
            }
        }
        if (more) {
            stageAB(cur ^ 1);
            __syncthreads();
            cur ^= 1;
        }
    }

    // ---- epilogue
    if (EMODE == 3) {
        // fused relu + dot(W2) partials. part[mt][half] = row partial over
        // this warp's 64-column slice.
        float part[2][2] = {{0.f, 0.f}, {0.f, 0.f}};
        #pragma unroll
        for (int nt = 0; nt < 8; ++nt) {
            int c0 = nBase + wn + nt * 8 + 2 * t4;
            float bi0 = __ldg(bias + c0),  bi1 = __ldg(bias + c0 + 1);
            float w20 = __ldg(W2 + c0),    w21 = __ldg(W2 + c0 + 1);
            #pragma unroll
            for (int mt = 0; mt < 2; ++mt) {
                part[mt][0] = fmaf(fmaxf(acc[mt][nt][0] + bi0, 0.f), w20, part[mt][0]);
                part[mt][0] = fmaf(fmaxf(acc[mt][nt][1] + bi1, 0.f), w21, part[mt][0]);
                part[mt][1] = fmaf(fmaxf(acc[mt][nt][2] + bi0, 0.f), w20, part[mt][1]);
                part[mt][1] = fmaf(fmaxf(acc[mt][nt][3] + bi1, 0.f), w21, part[mt][1]);
            }
        }
        #pragma unroll
        for (int mt = 0; mt < 2; ++mt)
            #pragma unroll
            for (int hf = 0; hf < 2; ++hf) {
                float v = part[mt][hf];
                v += __shfl_xor_sync(0xffffffffu, v, 1);
                v += __shfl_xor_sync(0xffffffffu, v, 2);
                part[mt][hf] = v;
            }
        if (t4 == 0) {
            #pragma unroll
            for (int mt = 0; mt < 2; ++mt)
                #pragma unroll
                for (int hf = 0; hf < 2; ++hf) {
                    long m = mBase + wm + mt * 16 + g + hf * 8;
                    C[m * 8 + blockIdx.x * 2 + (warp >> 2)] = part[mt][hf];
                }
        }
    } else {
        #pragma unroll
        for (int mt = 0; mt < 2; ++mt) {
            int r0 = mBase + wm + mt * 16 + g;
            #pragma unroll
            for (int nt = 0; nt < 8; ++nt) {
                int c0 = nBase + wn + nt * 8 + 2 * t4;
                #pragma unroll
                for (int half = 0; half < 2; ++half) {
                    int m = r0 + half * 8;
                    float v0 = acc[mt][nt][half*2 + 0];
                    float v1 = acc[mt][nt][half*2 + 1];
                    if (EMODE == 0) {
                        if (m < M) {
                            float* cp = C + (long)m * N + c0;
                            cp[0] = v0 + bias[c0];
                            cp[1] = v1 + bias[c0 + 1];
                        }
                    } else { // EMODE 1: qkv scatter
                        if (m < M) {
                            int b = m / NS, s = m % NS;
                            int hh0 = c0 >> 6, hd0 = c0 & 63;
                            float* cp = g_qkv + ((((long)b * NH + hh0) * NS + s) * HD + hd0);
                            long ofs = (long)(C - g_qkv);
                            cp += ofs;
                            cp[0] = v0 + bias[c0];
                            cp[1] = v1 + bias[c0 + 1];
                        }
                    }
                }
            }
        }
    }
}

// =====================================================================
// adv_finish: per (b,h): p2 (64), p1 (256), entropy, per-bh losses.
// =====================================================================
__global__ void adv_finish(const float* __restrict__ a2, const float* __restrict__ b2)
{
    __shared__ float sm_p2[64];
    __shared__ float sred1[8], sred2[8];
    const int bh = blockIdx.x;
    const int tid = threadIdx.x, lane = tid & 31, w = tid >> 5;

    // p2: threads 0..63
    float l2 = 0.f;
    if (tid < 64) {
        const float* pp = g_part2 + ((size_t)bh * 64 + tid) * 8;
        float s = b2[0];
        #pragma unroll
        for (int i = 0; i < 8; ++i) s += pp[i];
        float p = 1.f / (1.f + expf(-s));
        sm_p2[tid] = p;
        l2 = logf(fmaxf(1.f - p, EPSV));
    }
    // p1: every thread one token
    float l1;
    float p1v;
    {
        const float* pp = g_part1 + ((size_t)bh * 256 + tid) * 8;
        float s = a2[0];
        #pragma unroll
        for (int i = 0; i < 8; ++i) s += pp[i];
        p1v = 1.f / (1.f + expf(-s));
        l1 = logf(fmaxf(1.f - p1v, EPSV));
    }
    // warp reduce
    #pragma unroll
    for (int o = 16; o > 0; o >>= 1) {
        l1 += __shfl_xor_sync(0xffffffffu, l1, o);
        l2 += __shfl_xor_sync(0xffffffffu, l2, o);
    }
    if (lane == 0) { sred1[w] = l1; sred2[w] = l2; }
    __syncthreads();

    // entropy
    {
        int t = tid;
        int gr = t >> 4, gc = t & 15;
        int m  = (gr >> 1) * 8 + (gc >> 1);
        float ad  = (1.f - LAMDA) * p1v + LAMDA * sm_p2[m];
        float ent = -ad * log2f(ad + EPSV) - (1.f - ad) * log2f(1.f - ad + EPSV);
        g_ent[bh * NS + 1 + t] = ent;
    }
    if (tid == 0) {
        g_ent[bh * NS] = 1.f;
        float s1 = 0.f, s2 = 0.f;
        #pragma unroll
        for (int i = 0; i < 8; ++i) { s1 += sred1[i]; s2 += sred2[i]; }
        g_loss1[bh] = s1;
        g_loss2[bh] = s2;
    }
}

// =====================================================================
// Attention: one block per (b,h), 512 threads (16 warps).
// =====================================================================
__global__ void __launch_bounds__(512)
attn_kernel()
{
    extern __shared__ float sm[];
    float* sm_kT = sm;                    // [64][257]
    float* sm_v  = sm + 64*NS;            // [257][64]
    float* sm_p  = sm_v + NS*64;          // [16][257]

    const int bh   = blockIdx.x;
    const int tid  = threadIdx.x;
    const int lane = tid & 31;
    const int w    = tid >> 5;

    const float* qb = g_qkv + (size_t)bh * NS * HD;
    const float* kb = g_qkv + (size_t)NQKV + (size_t)bh * NS * HD;
    const float* vb = g_qkv + (size_t)2*NQKV + (size_t)bh * NS * HD;

    for (int i = tid; i < NS*64; i += 512) {
        int t = i >> 6, d = i & 63;
        sm_kT[d*NS + t] = kb[i];
        sm_v[i]         = vb[i];
    }
    __syncthreads();

    const int b = bh / NH, h = bh % NH;

    for (int s = w; s < NS; s += 16) {
        float q[64];
        #pragma unroll
        for (int d = 0; d < 64; ++d) q[d] = qb[s*64 + d];

        float sc[9];
        #pragma unroll
        for (int c = 0; c < 9; ++c) {
            int kt = lane + 32*c;
            float acc = -1e30f;
            if (kt < NS) {
                acc = 0.f;
                #pragma unroll
                for (int d = 0; d < 64; ++d)
                    acc = fmaf(q[d], sm_kT[d*NS + kt], acc);
                acc *= 0.125f;
            }
            sc[c] = acc;
        }
        float mx = sc[0];
        #pragma unroll
        for (int c = 1; c < 9; ++c) mx = fmaxf(mx, sc[c]);
        #pragma unroll
        for (int o = 16; o > 0; o >>= 1) mx = fmaxf(mx, __shfl_xor_sync(0xffffffffu, mx, o));

        float sum = 0.f;
        #pragma unroll
        for (int c = 0; c < 9; ++c) {
            int kt = lane + 32*c;
            float e = (kt < NS) ? expf(sc[c] - mx) : 0.f;
            sc[c] = e;
            sum += e;
        }
        #pragma unroll
        for (int o = 16; o > 0; o >>= 1) sum += __shfl_xor_sync(0xffffffffu, sum, o);
        float inv = 1.f / sum;

        __syncwarp();
        #pragma unroll
        for (int c = 0; c < 9; ++c) {
            int kt = lane + 32*c;
            if (kt < NS) {
                float p = sc[c] * inv;
                if (s == 0) p *= g_ent[bh*NS + kt];
                sm_p[w*NS + kt] = p;
            }
        }
        __syncwarp();

        float acc0 = 0.f, acc1 = 0.f;
        const float* pw = sm_p + w*NS;
        #pragma unroll 4
        for (int kt = 0; kt < 256; ++kt) {
            float pv = pw[kt];
            acc0 = fmaf(pv, sm_v[kt*64 + lane],      acc0);
            acc1 = fmaf(pv, sm_v[kt*64 + 32 + lane], acc1);
        }
        {
            float pv = pw[256];
            acc0 = fmaf(pv, sm_v[256*64 + lane],      acc0);
            acc1 = fmaf(pv, sm_v[256*64 + 32 + lane], acc1);
        }
        float* cp = g_ctx + ((size_t)(b*NS + s)) * ND + h*HD;
        cp[lane]      = acc0;
        cp[32 + lane] = acc1;
        __syncwarp();
    }
}

// =====================================================================
// Final deterministic loss reduction
// =====================================================================
__global__ void loss_kernel(float* __restrict__ out)
{
    __shared__ float s1[256], s2[256];
    int tid = threadIdx.x;
    float a = 0.f, b = 0.f;
    for (int i = tid; i < NBH; i += 256) { a += g_loss1[i]; b += g_loss2[i]; }
    s1[tid] = a; s2[tid] = b;
    __syncthreads();
    for (int o = 128; o > 0; o >>= 1) {
        if (tid < o) { s1[tid] += s1[tid + o]; s2[tid] += s2[tid + o]; }
        __syncthreads();
    }
    if (tid == 0)
        out[0] = -s1[0] / ((float)NBH * 256.f) - s2[0] / ((float)NBH * 64.f);
}

// =====================================================================
// Launch
// =====================================================================
extern "C" void kernel_launch(void* const* d_in, const int* in_sizes, int n_in,
                              void* d_out, int out_size)
{
    const float* X  = (const float*)d_in[0];
    const float* Wq = (const float*)d_in[1];
    const float* bq = (const float*)d_in[2];
    const float* Wk = (const float*)d_in[3];
    const float* bk = (const float*)d_in[4];
    const float* Wv = (const float*)d_in[5];
    const float* bv = (const float*)d_in[6];
    const float* Wo = (const float*)d_in[7];
    const float* bo = (const float*)d_in[8];
    const float* A1 = (const float*)d_in[9];
    const float* a1 = (const float*)d_in[10];
    const float* A2 = (const float*)d_in[11];
    const float* a2 = (const float*)d_in[12];
    const float* B1 = (const float*)d_in[13];
    const float* b1 = (const float*)d_in[14];
    const float* B2 = (const float*)d_in[15];
    const float* b2 = (const float*)d_in[16];
    float* out = (float*)d_out;

    float *qkv = nullptr, *ctx = nullptr, *pt1 = nullptr, *pt2 = nullptr;
    cudaGetSymbolAddress((void**)&qkv, g_qkv);
    cudaGetSymbolAddress((void**)&ctx, g_ctx);
    cudaGetSymbolAddress((void**)&pt1, g_part1);
    cudaGetSymbolAddress((void**)&pt2, g_part2);
    float* kbase = qkv + NQKV;

    const int ATTN_SMEM = (64*NS + NS*64 + 16*NS) * 4;   // 148032 B
    cudaFuncSetAttribute(attn_kernel, cudaFuncAttributeMaxDynamicSharedMemorySize, ATTN_SMEM);

    dim3 gproj(ND/128, (NTOK + 127)/128);   // (6, 129)

    gemm_tc<0,1><<<gproj, 256>>>(X, Wq, bq, nullptr, qkv,           NTOK, ND, ND);
    gemm_tc<0,1><<<gproj, 256>>>(X, Wk, bk, nullptr, qkv + NQKV,    NTOK, ND, ND);
    gemm_tc<0,1><<<gproj, 256>>>(X, Wv, bv, nullptr, qkv + 2*NQKV,  NTOK, ND, ND);

    // adversarial layer-1 GEMMs with fused relu+layer-2 partial dot
    gemm_tc<2,3><<<dim3(4, (NBH*256)/128), 256>>>(kbase, A1, a1, A2, pt1, NBH*256, 512, 64);
    gemm_tc<3,3><<<dim3(4, (NBH*64)/128),  256>>>(kbase, B1, b1, B2, pt2, NBH*64,  512, 256);

    adv_finish<<<NBH, 256>>>(a2, b2);

    attn_kernel<<<NBH, 512, ATTN_SMEM>>>();

    gemm_tc<0,0><<<gproj, 256>>>(ctx, Wo, bo, nullptr, out, NTOK, ND, ND);

    if (out_size > NQKV)
        loss_kernel<<<1, 256>>>(out + (out_size - 1));
}

// round 4
// speedup vs baseline: 2.1389x; 1.0003x over previous
#include <cuda_runtime.h>
#include <math.h>

#define NB 64
#define NS 257
#define ND 768
#define NH 12
#define HD 64
#define NTOK (NB*NS)          /* 16448 */
#define NQKV (NTOK*ND)        /* 12632064 */
#define NBH (NB*NH)           /* 768 */
#define EPSV 1e-10f
#define LAMDA 0.475f

// ---------------- device scratch ----------------
__device__ float g_qkv[3*NQKV];            // q | k | v, each (B,H,S,HD)
__device__ float g_ctx[NQKV];              // (B,S,D)
__device__ float g_ent[NBH*NS];            // entropy row, [0]=1
__device__ float g_loss1[NBH];
__device__ float g_loss2[NBH];
__device__ float g_part1[(size_t)NBH*256*8];  // p1 layer-2 partial dots
__device__ float g_part2[(size_t)NBH*64*8];   // p2 layer-2 partial dots

// ---------------- tf32 helpers ----------------
__device__ __forceinline__ unsigned f2tf32(float x){
    unsigned r; asm("cvt.rna.tf32.f32 %0, %1;" : "=r"(r) : "f"(x)); return r;
}
__device__ __forceinline__ void mma_tf32(float* c,
    unsigned a0, unsigned a1, unsigned a2, unsigned a3,
    unsigned b0, unsigned b1)
{
    asm volatile(
      "mma.sync.aligned.m16n8k8.row.col.f32.tf32.tf32.f32 "
      "{%0,%1,%2,%3},{%4,%5,%6,%7},{%8,%9},{%0,%1,%2,%3};"
      : "+f"(c[0]), "+f"(c[1]), "+f"(c[2]), "+f"(c[3])
      : "r"(a0), "r"(a1), "r"(a2), "r"(a3), "r"(b0), "r"(b1));
}

// =====================================================================
// Tensor-core tf32 GEMM: BM=128, BN=128, BK=16, 256 threads, smem 2-stage.
// AMODE 0: A row-major [M,K] (guarded)
// AMODE 2: p1 feature gather (row m -> bh,t in k tensor), lda=64
// AMODE 3: p2 merged-patch gather (K=256 -> q,d decomposition)
// EMODE 0: C row-major + bias
// EMODE 1: qkv scatter (B,H,S,HD) + bias
// EMODE 3: fused relu + dot with W2 -> per-(row, col-slice) partials in C
// =====================================================================
template<int AMODE, int EMODE>
__global__ void __launch_bounds__(256)
gemm_tc(const float* __restrict__ A, const float* __restrict__ W,
        const float* __restrict__ bias, const float* __restrict__ W2,
        float* __restrict__ C, int M, int N, int K)
{
    __shared__ unsigned As[2][16][132];
    __shared__ unsigned Bs[2][16][132];

    const int tid  = threadIdx.x;
    const int lane = tid & 31;
    const int warp = tid >> 5;
    const int g    = lane >> 2;
    const int t4   = lane & 3;
    const int wm   = (warp & 3) * 32;
    const int wn   = (warp >> 2) * 64;
    const int mBase = blockIdx.y * 128;
    const int nBase = blockIdx.x * 128;

    const int aRow = tid >> 1;
    const int aK   = (tid & 1) * 8;
    const int bRow = tid >> 4;
    const int bCol = (tid & 15) * 8;

    long aOff = -1;
    int  rowbase = 0, pr2 = 0, pc2 = 0;
    if (AMODE == 0) {
        int m = mBase + aRow;
        if (m < M) aOff = (long)m * K;
    } else if (AMODE == 2) {
        int m  = mBase + aRow;
        int bh = m >> 8, t = m & 255;
        aOff = ((long)bh * NS + 1 + t) * HD;
    } else { // AMODE 3
        int m  = mBase + aRow;
        int bh = m >> 6, patch = m & 63;
        rowbase = bh * NS + 1;
        pr2 = patch >> 3; pc2 = patch & 7;
    }

    float ra[8], rb[8];

    auto loadAB = [&](int k0) {
        if (AMODE == 3) {
            int kk = k0 + aK;
            int q = kk >> 6, d = kk & 63;
            int token = (2*pr2 + (q >> 1)) * 16 + 2*pc2 + (q & 1);
            const float4* p = (const float4*)(A + ((long)(rowbase + token)) * HD + d);
            float4 v0 = p[0], v1 = p[1];
            ra[0]=v0.x; ra[1]=v0.y; ra[2]=v0.z; ra[3]=v0.w;
            ra[4]=v1.x; ra[5]=v1.y; ra[6]=v1.z; ra[7]=v1.w;
        } else {
            if (aOff >= 0) {
                const float4* p = (const float4*)(A + aOff + k0 + aK);
                float4 v0 = p[0], v1 = p[1];
                ra[0]=v0.x; ra[1]=v0.y; ra[2]=v0.z; ra[3]=v0.w;
                ra[4]=v1.x; ra[5]=v1.y; ra[6]=v1.z; ra[7]=v1.w;
            } else {
                #pragma unroll
                for (int j = 0; j < 8; ++j) ra[j] = 0.f;
            }
        }
        const float4* p = (const float4*)(W + (long)(k0 + bRow) * N + nBase + bCol);
        float4 v0 = p[0], v1 = p[1];
        rb[0]=v0.x; rb[1]=v0.y; rb[2]=v0.z; rb[3]=v0.w;
        rb[4]=v1.x; rb[5]=v1.y; rb[6]=v1.z; rb[7]=v1.w;
    };
    auto stageAB = [&](int buf) {
        #pragma unroll
        for (int j = 0; j < 8; ++j) As[buf][aK + j][aRow] = f2tf32(ra[j]);
        #pragma unroll
        for (int j = 0; j < 8; ++j) Bs[buf][bRow][bCol + j] = f2tf32(rb[j]);
    };

    float acc[2][8][4];
    #pragma unroll
    for (int mt = 0; mt < 2; ++mt)
        #pragma unroll
        for (int nt = 0; nt < 8; ++nt)
            #pragma unroll
            for (int i = 0; i < 4; ++i) acc[mt][nt][i] = 0.f;

    loadAB(0);
    stageAB(0);
    __syncthreads();
    int cur = 0;

    for (int k0 = 0; k0 < K; k0 += 16) {
        const bool more = (k0 + 16) < K;
        if (more) loadAB(k0 + 16);

        #pragma unroll
        for (int ks = 0; ks < 2; ++ks) {
            const int kr = ks * 8;
            unsigned af[2][4];
            #pragma unroll
            for (int mt = 0; mt < 2; ++mt) {
                int m0 = wm + mt * 16;
                af[mt][0] = As[cur][kr + t4    ][m0 + g    ];
                af[mt][1] = As[cur][kr + t4    ][m0 + g + 8];
                af[mt][2] = As[cur][kr + t4 + 4][m0 + g    ];
                af[mt][3] = As[cur][kr + t4 + 4][m0 + g + 8];
            }
            #pragma unroll
            for (int nt = 0; nt < 8; ++nt) {
                int n0 = wn + nt * 8 + g;
                unsigned b0 = Bs[cur][kr + t4    ][n0];
                unsigned b1 = Bs[cur][kr + t4 + 4][n0];
                mma_tf32(acc[0][nt], af[0][0], af[0][1], af[0][2], af[0][3], b0, b1);
                mma_tf32(acc[1][nt], af[1][0], af[1][1], af[1][2], af[1][3], b0, b1);
            }
        }
        if (more) {
            stageAB(cur ^ 1);
            __syncthreads();
            cur ^= 1;
        }
    }

    // ---- epilogue
    if (EMODE == 3) {
        // fused relu + dot(W2) partials. part[mt][half] = row partial over
        // this warp's 64-column slice.
        float part[2][2] = {{0.f, 0.f}, {0.f, 0.f}};
        #pragma unroll
        for (int nt = 0; nt < 8; ++nt) {
            int c0 = nBase + wn + nt * 8 + 2 * t4;
            float bi0 = __ldg(bias + c0),  bi1 = __ldg(bias + c0 + 1);
            float w20 = __ldg(W2 + c0),    w21 = __ldg(W2 + c0 + 1);
            #pragma unroll
            for (int mt = 0; mt < 2; ++mt) {
                part[mt][0] = fmaf(fmaxf(acc[mt][nt][0] + bi0, 0.f), w20, part[mt][0]);
                part[mt][0] = fmaf(fmaxf(acc[mt][nt][1] + bi1, 0.f), w21, part[mt][0]);
                part[mt][1] = fmaf(fmaxf(acc[mt][nt][2] + bi0, 0.f), w20, part[mt][1]);
                part[mt][1] = fmaf(fmaxf(acc[mt][nt][3] + bi1, 0.f), w21, part[mt][1]);
            }
        }
        #pragma unroll
        for (int mt = 0; mt < 2; ++mt)
            #pragma unroll
            for (int hf = 0; hf < 2; ++hf) {
                float v = part[mt][hf];
                v += __shfl_xor_sync(0xffffffffu, v, 1);
                v += __shfl_xor_sync(0xffffffffu, v, 2);
                part[mt][hf] = v;
            }
        if (t4 == 0) {
            #pragma unroll
            for (int mt = 0; mt < 2; ++mt)
                #pragma unroll
                for (int hf = 0; hf < 2; ++hf) {
                    long m = mBase + wm + mt * 16 + g + hf * 8;
                    C[m * 8 + blockIdx.x * 2 + (warp >> 2)] = part[mt][hf];
                }
        }
    } else {
        #pragma unroll
        for (int mt = 0; mt < 2; ++mt) {
            int r0 = mBase + wm + mt * 16 + g;
            #pragma unroll
            for (int nt = 0; nt < 8; ++nt) {
                int c0 = nBase + wn + nt * 8 + 2 * t4;
                #pragma unroll
                for (int half = 0; half < 2; ++half) {
                    int m = r0 + half * 8;
                    float v0 = acc[mt][nt][half*2 + 0];
                    float v1 = acc[mt][nt][half*2 + 1];
                    if (EMODE == 0) {
                        if (m < M) {
                            float* cp = C + (long)m * N + c0;
                            cp[0] = v0 + bias[c0];
                            cp[1] = v1 + bias[c0 + 1];
                        }
                    } else { // EMODE 1: qkv scatter
                        if (m < M) {
                            int b = m / NS, s = m % NS;
                            int hh0 = c0 >> 6, hd0 = c0 & 63;
                            float* cp = g_qkv + ((((long)b * NH + hh0) * NS + s) * HD + hd0);
                            long ofs = (long)(C - g_qkv);
                            cp += ofs;
                            cp[0] = v0 + bias[c0];
                            cp[1] = v1 + bias[c0 + 1];
                        }
                    }
                }
            }
        }
    }
}

// =====================================================================
// adv_finish: per (b,h): p2 (64), p1 (256), entropy, per-bh losses.
// =====================================================================
__global__ void adv_finish(const float* __restrict__ a2, const float* __restrict__ b2)
{
    __shared__ float sm_p2[64];
    __shared__ float sred1[8], sred2[8];
    const int bh = blockIdx.x;
    const int tid = threadIdx.x, lane = tid & 31, w = tid >> 5;

    // p2: threads 0..63
    float l2 = 0.f;
    if (tid < 64) {
        const float* pp = g_part2 + ((size_t)bh * 64 + tid) * 8;
        float s = b2[0];
        #pragma unroll
        for (int i = 0; i < 8; ++i) s += pp[i];
        float p = 1.f / (1.f + expf(-s));
        sm_p2[tid] = p;
        l2 = logf(fmaxf(1.f - p, EPSV));
    }
    // p1: every thread one token
    float l1;
    float p1v;
    {
        const float* pp = g_part1 + ((size_t)bh * 256 + tid) * 8;
        float s = a2[0];
        #pragma unroll
        for (int i = 0; i < 8; ++i) s += pp[i];
        p1v = 1.f / (1.f + expf(-s));
        l1 = logf(fmaxf(1.f - p1v, EPSV));
    }
    // warp reduce
    #pragma unroll
    for (int o = 16; o > 0; o >>= 1) {
        l1 += __shfl_xor_sync(0xffffffffu, l1, o);
        l2 += __shfl_xor_sync(0xffffffffu, l2, o);
    }
    if (lane == 0) { sred1[w] = l1; sred2[w] = l2; }
    __syncthreads();

    // entropy
    {
        int t = tid;
        int gr = t >> 4, gc = t & 15;
        int m  = (gr >> 1) * 8 + (gc >> 1);
        float ad  = (1.f - LAMDA) * p1v + LAMDA * sm_p2[m];
        float ent = -ad * log2f(ad + EPSV) - (1.f - ad) * log2f(1.f - ad + EPSV);
        g_ent[bh * NS + 1 + t] = ent;
    }
    if (tid == 0) {
        g_ent[bh * NS] = 1.f;
        float s1 = 0.f, s2 = 0.f;
        #pragma unroll
        for (int i = 0; i < 8; ++i) { s1 += sred1[i]; s2 += sred2[i]; }
        g_loss1[bh] = s1;
        g_loss2[bh] = s2;
    }
}

// =====================================================================
// Attention: one block per (b,h), 512 threads (16 warps).
// =====================================================================
__global__ void __launch_bounds__(512)
attn_kernel()
{
    extern __shared__ float sm[];
    float* sm_kT = sm;                    // [64][257]
    float* sm_v  = sm + 64*NS;            // [257][64]
    float* sm_p  = sm_v + NS*64;          // [16][257]

    const int bh   = blockIdx.x;
    const int tid  = threadIdx.x;
    const int lane = tid & 31;
    const int w    = tid >> 5;

    const float* qb = g_qkv + (size_t)bh * NS * HD;
    const float* kb = g_qkv + (size_t)NQKV + (size_t)bh * NS * HD;
    const float* vb = g_qkv + (size_t)2*NQKV + (size_t)bh * NS * HD;

    for (int i = tid; i < NS*64; i += 512) {
        int t = i >> 6, d = i & 63;
        sm_kT[d*NS + t] = kb[i];
        sm_v[i]         = vb[i];
    }
    __syncthreads();

    const int b = bh / NH, h = bh % NH;

    for (int s = w; s < NS; s += 16) {
        float q[64];
        #pragma unroll
        for (int d = 0; d < 64; ++d) q[d] = qb[s*64 + d];

        float sc[9];
        #pragma unroll
        for (int c = 0; c < 9; ++c) {
            int kt = lane + 32*c;
            float acc = -1e30f;
            if (kt < NS) {
                acc = 0.f;
                #pragma unroll
                for (int d = 0; d < 64; ++d)
                    acc = fmaf(q[d], sm_kT[d*NS + kt], acc);
                acc *= 0.125f;
            }
            sc[c] = acc;
        }
        float mx = sc[0];
        #pragma unroll
        for (int c = 1; c < 9; ++c) mx = fmaxf(mx, sc[c]);
        #pragma unroll
        for (int o = 16; o > 0; o >>= 1) mx = fmaxf(mx, __shfl_xor_sync(0xffffffffu, mx, o));

        float sum = 0.f;
        #pragma unroll
        for (int c = 0; c < 9; ++c) {
            int kt = lane + 32*c;
            float e = (kt < NS) ? expf(sc[c] - mx) : 0.f;
            sc[c] = e;
            sum += e;
        }
        #pragma unroll
        for (int o = 16; o > 0; o >>= 1) sum += __shfl_xor_sync(0xffffffffu, sum, o);
        float inv = 1.f / sum;

        __syncwarp();
        #pragma unroll
        for (int c = 0; c < 9; ++c) {
            int kt = lane + 32*c;
            if (kt < NS) {
                float p = sc[c] * inv;
                if (s == 0) p *= g_ent[bh*NS + kt];
                sm_p[w*NS + kt] = p;
            }
        }
        __syncwarp();

        float acc0 = 0.f, acc1 = 0.f;
        const float* pw = sm_p + w*NS;
        #pragma unroll 4
        for (int kt = 0; kt < 256; ++kt) {
            float pv = pw[kt];
            acc0 = fmaf(pv, sm_v[kt*64 + lane],      acc0);
            acc1 = fmaf(pv, sm_v[kt*64 + 32 + lane], acc1);
        }
        {
            float pv = pw[256];
            acc0 = fmaf(pv, sm_v[256*64 + lane],      acc0);
            acc1 = fmaf(pv, sm_v[256*64 + 32 + lane], acc1);
        }
        float* cp = g_ctx + ((size_t)(b*NS + s)) * ND + h*HD;
        cp[lane]      = acc0;
        cp[32 + lane] = acc1;
        __syncwarp();
    }
}

// =====================================================================
// Final deterministic loss reduction
// =====================================================================
__global__ void loss_kernel(float* __restrict__ out)
{
    __shared__ float s1[256], s2[256];
    int tid = threadIdx.x;
    float a = 0.f, b = 0.f;
    for (int i = tid; i < NBH; i += 256) { a += g_loss1[i]; b += g_loss2[i]; }
    s1[tid] = a; s2[tid] = b;
    __syncthreads();
    for (int o = 128; o > 0; o >>= 1) {
        if (tid < o) { s1[tid] += s1[tid + o]; s2[tid] += s2[tid + o]; }
        __syncthreads();
    }
    if (tid == 0)
        out[0] = -s1[0] / ((float)NBH * 256.f) - s2[0] / ((float)NBH * 64.f);
}

// =====================================================================
// Launch
// =====================================================================
extern "C" void kernel_launch(void* const* d_in, const int* in_sizes, int n_in,
                              void* d_out, int out_size)
{
    const float* X  = (const float*)d_in[0];
    const float* Wq = (const float*)d_in[1];
    const float* bq = (const float*)d_in[2];
    const float* Wk = (const float*)d_in[3];
    const float* bk = (const float*)d_in[4];
    const float* Wv = (const float*)d_in[5];
    const float* bv = (const float*)d_in[6];
    const float* Wo = (const float*)d_in[7];
    const float* bo = (const float*)d_in[8];
    const float* A1 = (const float*)d_in[9];
    const float* a1 = (const float*)d_in[10];
    const float* A2 = (const float*)d_in[11];
    const float* a2 = (const float*)d_in[12];
    const float* B1 = (const float*)d_in[13];
    const float* b1 = (const float*)d_in[14];
    const float* B2 = (const float*)d_in[15];
    const float* b2 = (const float*)d_in[16];
    float* out = (float*)d_out;

    float *qkv = nullptr, *ctx = nullptr, *pt1 = nullptr, *pt2 = nullptr;
    cudaGetSymbolAddress((void**)&qkv, g_qkv);
    cudaGetSymbolAddress((void**)&ctx, g_ctx);
    cudaGetSymbolAddress((void**)&pt1, g_part1);
    cudaGetSymbolAddress((void**)&pt2, g_part2);
    float* kbase = qkv + NQKV;

    const int ATTN_SMEM = (64*NS + NS*64 + 16*NS) * 4;   // 148032 B
    cudaFuncSetAttribute(attn_kernel, cudaFuncAttributeMaxDynamicSharedMemorySize, ATTN_SMEM);

    dim3 gproj(ND/128, (NTOK + 127)/128);   // (6, 129)

    gemm_tc<0,1><<<gproj, 256>>>(X, Wq, bq, nullptr, qkv,           NTOK, ND, ND);
    gemm_tc<0,1><<<gproj, 256>>>(X, Wk, bk, nullptr, qkv + NQKV,    NTOK, ND, ND);
    gemm_tc<0,1><<<gproj, 256>>>(X, Wv, bv, nullptr, qkv + 2*NQKV,  NTOK, ND, ND);

    // adversarial layer-1 GEMMs with fused relu+layer-2 partial dot
    gemm_tc<2,3><<<dim3(4, (NBH*256)/128), 256>>>(kbase, A1, a1, A2, pt1, NBH*256, 512, 64);
    gemm_tc<3,3><<<dim3(4, (NBH*64)/128),  256>>>(kbase, B1, b1, B2, pt2, NBH*64,  512, 256);

    adv_finish<<<NBH, 256>>>(a2, b2);

    attn_kernel<<<NBH, 512, ATTN_SMEM>>>();

    gemm_tc<0,0><<<gproj, 256>>>(ctx, Wo, bo, nullptr, out, NTOK, ND, ND);

    if (out_size > NQKV)
        loss_kernel<<<1, 256>>>(out + (out_size - 1));
}